// round 8
// baseline (speedup 1.0000x reference)
#include <cuda_runtime.h>
#include <cuda_bf16.h>
#include <cstdint>

// RVQ: x [16,2048,128] f32, codebooks [8,1024,128] f32
// out (float32): indices [B*N*Q] ++ quantized [B*N*D] ++ commits [Q]
// Core: bf16 3-term-split distance GEMM (HMMA mma.sync) + exact fp32 top-2 rescue.

#define TOKENS   32768
#define DDIM     128
#define KCODES   1024
#define QSTAGES  8
#define BM       128
#define NTILE    64
#define NTILES   (KCODES / NTILE)   // 16
#define NTHREADS 256
#define NBLOCKS  (TOKENS / BM)      // 256

#define A_TERM_BYTES 32768   // 128 rows x 256 B
#define B_TERM_BYTES 16384   // 64 rows x 256 B
#define A_OFF        0
#define B_OFF        98304   // 3 * A_TERM_BYTES
#define B_BUF_BYTES  49152   // 3 * B_TERM_BYTES
#define CHOSEN_OFF   196608
#define REDV_OFF     197120  // [2][128] best
#define REDI_OFF     198144
#define REDV2_OFF    199168  // [2][128] runner-up
#define REDI2_OFF    200192
#define SMEM_TOTAL   201216

__device__ float g_res[TOKENS * DDIM];
__device__ float g_c2[QSTAGES * KCODES];
__device__ float g_partial[QSTAGES * NBLOCKS];
__device__ unsigned char g_cbs[(size_t)QSTAGES * NTILES * 3 * B_TERM_BYTES];

// ---------------------------------------------------------------------------
__device__ __forceinline__ void cp16(uint32_t dst, const void* src) {
    asm volatile("cp.async.cg.shared.global [%0], [%1], 16;" :: "r"(dst), "l"(src));
}
__device__ __forceinline__ void cp_commit() { asm volatile("cp.async.commit_group;"); }
template<int N> __device__ __forceinline__ void cp_wait() {
    asm volatile("cp.async.wait_group %0;" :: "n"(N) : "memory");
}
__device__ __forceinline__ uint32_t smem_u32(const void* p) {
    uint32_t a;
    asm("{ .reg .u64 t; cvta.to.shared.u64 t, %1; cvt.u32.u64 %0, t; }" : "=r"(a) : "l"(p));
    return a;
}
__device__ __forceinline__ void ldsm4(uint32_t& r0, uint32_t& r1, uint32_t& r2,
                                      uint32_t& r3, uint32_t addr) {
    asm volatile("ldmatrix.sync.aligned.m8n8.x4.shared.b16 {%0,%1,%2,%3}, [%4];"
                 : "=r"(r0), "=r"(r1), "=r"(r2), "=r"(r3) : "r"(addr));
}
__device__ __forceinline__ void mma16816(float& d0, float& d1, float& d2, float& d3,
                                         uint32_t a0, uint32_t a1, uint32_t a2,
                                         uint32_t a3, uint32_t b0, uint32_t b1) {
    asm volatile(
        "mma.sync.aligned.m16n8k16.row.col.f32.bf16.bf16.f32 "
        "{%0,%1,%2,%3}, {%4,%5,%6,%7}, {%8,%9}, {%0,%1,%2,%3};"
        : "+f"(d0), "+f"(d1), "+f"(d2), "+f"(d3)
        : "r"(a0), "r"(a1), "r"(a2), "r"(a3), "r"(b0), "r"(b1));
}
__device__ __forceinline__ bool dless(float a, int ia, float b, int ib) {
    return a < b || (a == b && ia < ib);
}
// merge other (o1,oj1,o2,oj2) into (v1,j1,v2,j2): keep global top-2
__device__ __forceinline__ void merge2(float& v1, int& j1, float& v2, int& j2,
                                       float o1, int oj1, float o2, int oj2) {
    float nv1, nv2; int nj1, nj2;
    if (dless(o1, oj1, v1, j1)) {
        nv1 = o1; nj1 = oj1;
        if (dless(v1, j1, o2, oj2)) { nv2 = v1; nj2 = j1; }
        else                        { nv2 = o2; nj2 = oj2; }
    } else {
        nv1 = v1; nj1 = j1;
        if (dless(o1, oj1, v2, j2)) { nv2 = o1; nj2 = oj1; }
        else                        { nv2 = v2; nj2 = j2; }
    }
    v1 = nv1; j1 = nj1; v2 = nv2; j2 = nj2;
}

// smem element (row, bf16-col c) -> byte:  r*256 + ((c>>3) ^ (r&7))*16 + (c&7)*2
__device__ __forceinline__ void split3(float4 v, uint2& H, uint2& M, uint2& L) {
    float a[4] = {v.x, v.y, v.z, v.w};
    unsigned short hs[4], ms[4], ls[4];
    #pragma unroll
    for (int i = 0; i < 4; i++) {
        __nv_bfloat16 hb = __float2bfloat16_rn(a[i]);
        float r1 = a[i] - __bfloat162float(hb);
        __nv_bfloat16 mb = __float2bfloat16_rn(r1);
        float r2 = r1 - __bfloat162float(mb);
        __nv_bfloat16 lb = __float2bfloat16_rn(r2);
        hs[i] = __bfloat16_as_ushort(hb);
        ms[i] = __bfloat16_as_ushort(mb);
        ls[i] = __bfloat16_as_ushort(lb);
    }
    H.x = hs[0] | ((uint32_t)hs[1] << 16); H.y = hs[2] | ((uint32_t)hs[3] << 16);
    M.x = ms[0] | ((uint32_t)ms[1] << 16); M.y = ms[2] | ((uint32_t)ms[3] << 16);
    L.x = ls[0] | ((uint32_t)ls[1] << 16); L.y = ls[2] | ((uint32_t)ls[3] << 16);
}

// ---------------------------------------------------------------------------
__global__ void prep_kernel(const float* __restrict__ cb) {
    int gr = blockIdx.x * blockDim.x + threadIdx.x;   // 0..8191
    if (gr >= QSTAGES * KCODES) return;
    int stage = gr >> 10, row = gr & 1023;
    int tile = row >> 6, r = row & 63;
    const float4* src = (const float4*)(cb + (size_t)gr * DDIM);
    unsigned char* base0 = g_cbs + (size_t)((stage * NTILES + tile) * 3) * B_TERM_BYTES;
    #pragma unroll 4
    for (int c4 = 0; c4 < 32; c4++) {
        uint2 H, M, L;
        split3(src[c4], H, M, L);
        uint32_t so = (uint32_t)r * 256 + (uint32_t)(((c4 >> 1) ^ (r & 7)) * 16)
                    + (uint32_t)((c4 & 1) * 8);
        *(uint2*)(base0 + so)                    = H;
        *(uint2*)(base0 + B_TERM_BYTES + so)     = M;
        *(uint2*)(base0 + 2 * B_TERM_BYTES + so) = L;
    }
}

// ---------------------------------------------------------------------------
__global__ void c2_kernel(const float* __restrict__ cb) {
    int warp = (blockIdx.x * blockDim.x + threadIdx.x) >> 5;
    int lane = threadIdx.x & 31;
    const float4* row = (const float4*)(cb + (size_t)warp * DDIM);
    float4 v = row[lane];
    float s = v.x * v.x + v.y * v.y + v.z * v.z + v.w * v.w;
    #pragma unroll
    for (int o = 16; o > 0; o >>= 1) s += __shfl_down_sync(0xffffffffu, s, o);
    if (lane == 0) g_c2[warp] = s;
}

// ---------------------------------------------------------------------------
extern __shared__ char sm[];

__global__ __launch_bounds__(NTHREADS, 1)
void stage_kernel(const float* __restrict__ x,
                  const float* __restrict__ cb_all,
                  float* __restrict__ out,
                  int stage, int is_last) {
    const uint32_t smb = smem_u32(sm);
    const int tid = threadIdx.x, wid = tid >> 5, lid = tid & 31;
    const int tok0 = blockIdx.x * BM;
    const int warpM = wid & 3, warpN = wid >> 2;   // 4 x 2 warp grid
    const float*  src = (stage == 0) ? x : (const float*)g_res;
    const float*  cbf = cb_all + (size_t)stage * KCODES * DDIM;
    const float4* cb4 = (const float4*)cbf;
    const float*  c2  = g_c2 + stage * KCODES;

    int*   chosen = (int*)(sm + CHOSEN_OFF);
    float* redv   = (float*)(sm + REDV_OFF);
    int*   redi   = (int*)(sm + REDI_OFF);
    float* redv2  = (float*)(sm + REDV2_OFF);
    int*   redi2  = (int*)(sm + REDI2_OFF);

    // ---- preload B tiles 0,1 ----
    const unsigned char* gcb = g_cbs + (size_t)(stage * NTILES * 3) * B_TERM_BYTES;
    {
        uint32_t b0 = smb + B_OFF, b1 = smb + B_OFF + B_BUF_BYTES;
        #pragma unroll
        for (int k = 0; k < 12; k++) {
            int u = tid + k * NTHREADS;
            cp16(b0 + (uint32_t)u * 16, gcb + (size_t)u * 16);
        }
        cp_commit();
        #pragma unroll
        for (int k = 0; k < 12; k++) {
            int u = tid + k * NTHREADS;
            cp16(b1 + (uint32_t)u * 16, gcb + B_BUF_BYTES + (size_t)u * 16);
        }
        cp_commit();
    }

    // ---- A split: residual -> 3 bf16 terms in swizzled smem ----
    {
        const float4* s4 = (const float4*)src + (size_t)tok0 * 32;
        #pragma unroll
        for (int k = 0; k < 16; k++) {
            int f = tid + k * NTHREADS;
            int r = f >> 5, c4 = f & 31;
            uint2 H, M, L;
            split3(s4[f], H, M, L);
            uint32_t so = (uint32_t)r * 256 + (uint32_t)(((c4 >> 1) ^ (r & 7)) * 16)
                        + (uint32_t)((c4 & 1) * 8);
            *(uint2*)(sm + A_OFF + so)                    = H;
            *(uint2*)(sm + A_OFF + A_TERM_BYTES + so)     = M;
            *(uint2*)(sm + A_OFF + 2 * A_TERM_BYTES + so) = L;
        }
    }
    __syncthreads();

    // ldmatrix lane address components
    uint32_t aRowByte[2], aRx[2];
    #pragma unroll
    for (int mi = 0; mi < 2; mi++) {
        int row = warpM * 32 + mi * 16 + (lid & 15);
        aRowByte[mi] = (uint32_t)row * 256;
        aRx[mi] = (uint32_t)(row & 7);
    }
    const uint32_t aKh = (uint32_t)(lid >> 4);
    uint32_t bRowByte[2], bRx[2];
    #pragma unroll
    for (int pi = 0; pi < 2; pi++) {
        int row = warpN * 32 + pi * 16 + ((lid >> 4) << 3) + (lid & 7);
        bRowByte[pi] = (uint32_t)row * 256;
        bRx[pi] = (uint32_t)(row & 7);
    }
    const uint32_t bKh = (uint32_t)((lid >> 3) & 1);

    const int pa[6] = {0, 0, 1, 1, 0, 2};
    const int pb[6] = {0, 1, 0, 1, 2, 0};

    // per-thread running TOP-2 per (mi, half)
    float b1v[2][2], b2v[2][2]; int b1i[2][2], b2i[2][2];
    #pragma unroll
    for (int mi = 0; mi < 2; mi++)
        #pragma unroll
        for (int h = 0; h < 2; h++) {
            b1v[mi][h] = 3.4e38f; b2v[mi][h] = 3.4e38f;
            b1i[mi][h] = 0;       b2i[mi][h] = 0;
        }

    for (int t = 0; t < NTILES; t++) {
        if (t < NTILES - 1) cp_wait<1>(); else cp_wait<0>();
        __syncthreads();
        const uint32_t bbuf = smb + B_OFF + (uint32_t)(t & 1) * B_BUF_BYTES;

        float acc[2][4][4];
        #pragma unroll
        for (int mi = 0; mi < 2; mi++)
            #pragma unroll
            for (int ni = 0; ni < 4; ni++)
                #pragma unroll
                for (int q = 0; q < 4; q++) acc[mi][ni][q] = 0.f;

        #pragma unroll
        for (int p = 0; p < 6; p++) {
            const uint32_t abase = smb + A_OFF + (uint32_t)pa[p] * A_TERM_BYTES;
            const uint32_t bbase = bbuf + (uint32_t)pb[p] * B_TERM_BYTES;
            #pragma unroll
            for (int k8 = 0; k8 < 8; k8++) {
                const uint32_t ku = (uint32_t)(k8 * 2);
                uint32_t a[2][4];
                #pragma unroll
                for (int mi = 0; mi < 2; mi++) {
                    uint32_t addr = abase + aRowByte[mi] + (((ku + aKh) ^ aRx[mi]) << 4);
                    ldsm4(a[mi][0], a[mi][1], a[mi][2], a[mi][3], addr);
                }
                uint32_t b[2][4];
                #pragma unroll
                for (int pi = 0; pi < 2; pi++) {
                    uint32_t addr = bbase + bRowByte[pi] + (((ku + bKh) ^ bRx[pi]) << 4);
                    ldsm4(b[pi][0], b[pi][1], b[pi][2], b[pi][3], addr);
                }
                #pragma unroll
                for (int mi = 0; mi < 2; mi++)
                    #pragma unroll
                    for (int pi = 0; pi < 2; pi++) {
                        mma16816(acc[mi][pi*2][0], acc[mi][pi*2][1],
                                 acc[mi][pi*2][2], acc[mi][pi*2][3],
                                 a[mi][0], a[mi][1], a[mi][2], a[mi][3],
                                 b[pi][0], b[pi][1]);
                        mma16816(acc[mi][pi*2+1][0], acc[mi][pi*2+1][1],
                                 acc[mi][pi*2+1][2], acc[mi][pi*2+1][3],
                                 a[mi][0], a[mi][1], a[mi][2], a[mi][3],
                                 b[pi][2], b[pi][3]);
                    }
            }
        }

        // top-2 argmin epilogue (ascending code order)
        const int codebase = t * NTILE + warpN * 32;
        #pragma unroll
        for (int ni = 0; ni < 4; ni++) {
            int code0 = codebase + ni * 8 + (lid & 3) * 2;
            float2 cc = __ldg((const float2*)(c2 + code0));
            #pragma unroll
            for (int mi = 0; mi < 2; mi++) {
                #pragma unroll
                for (int h = 0; h < 2; h++) {
                    float d0 = cc.x - 2.f * acc[mi][ni][h * 2];
                    float d1 = cc.y - 2.f * acc[mi][ni][h * 2 + 1];
                    if (d0 < b1v[mi][h]) {
                        b2v[mi][h] = b1v[mi][h]; b2i[mi][h] = b1i[mi][h];
                        b1v[mi][h] = d0; b1i[mi][h] = code0;
                    } else if (d0 < b2v[mi][h]) { b2v[mi][h] = d0; b2i[mi][h] = code0; }
                    if (d1 < b1v[mi][h]) {
                        b2v[mi][h] = b1v[mi][h]; b2i[mi][h] = b1i[mi][h];
                        b1v[mi][h] = d1; b1i[mi][h] = code0 + 1;
                    } else if (d1 < b2v[mi][h]) { b2v[mi][h] = d1; b2i[mi][h] = code0 + 1; }
                }
            }
        }

        __syncthreads();
        if (t + 2 < NTILES) {
            uint32_t bb = smb + B_OFF + (uint32_t)(t & 1) * B_BUF_BYTES;
            const unsigned char* gs = gcb + (size_t)(t + 2) * B_BUF_BYTES;
            #pragma unroll
            for (int k = 0; k < 12; k++) {
                int u = tid + k * NTHREADS;
                cp16(bb + (uint32_t)u * 16, gs + (size_t)u * 16);
            }
            cp_commit();
        }
    }

    // quad reduce with top-2 merge (lanes sharing rows differ in bits 0-1)
    #pragma unroll
    for (int mi = 0; mi < 2; mi++)
        #pragma unroll
        for (int h = 0; h < 2; h++) {
            float v1 = b1v[mi][h], v2 = b2v[mi][h];
            int   j1 = b1i[mi][h], j2 = b2i[mi][h];
            #pragma unroll
            for (int off = 1; off <= 2; off <<= 1) {
                float o1 = __shfl_xor_sync(0xffffffffu, v1, off);
                int   oj1 = __shfl_xor_sync(0xffffffffu, j1, off);
                float o2 = __shfl_xor_sync(0xffffffffu, v2, off);
                int   oj2 = __shfl_xor_sync(0xffffffffu, j2, off);
                merge2(v1, j1, v2, j2, o1, oj1, o2, oj2);
            }
            if ((lid & 3) == 0) {
                int row = warpM * 32 + mi * 16 + h * 8 + (lid >> 2);
                redv[warpN * 128 + row]  = v1;
                redi[warpN * 128 + row]  = j1;
                redv2[warpN * 128 + row] = v2;
                redi2[warpN * 128 + row] = j2;
            }
        }
    __syncthreads();
    if (tid < BM) {
        float v1 = redv[tid], v2 = redv2[tid];
        int   j1 = redi[tid], j2 = redi2[tid];
        merge2(v1, j1, v2, j2, redv[128 + tid], redi[128 + tid],
               redv2[128 + tid], redi2[128 + tid]);
        // exact fp32 rescue of the top-2 candidates
        const float* rrow = src + (size_t)(tok0 + tid) * DDIM;
        const float* c1row = cbf + (size_t)j1 * DDIM;
        const float* c2row = cbf + (size_t)j2 * DDIM;
        float acc1 = 0.f, acc2 = 0.f;
        #pragma unroll 16
        for (int d = 0; d < DDIM; d++) {
            float r = rrow[d];
            acc1 = fmaf(r, __ldg(&c1row[d]), acc1);
            acc2 = fmaf(r, __ldg(&c2row[d]), acc2);
        }
        float e1 = __ldg(&c2[j1]) - 2.f * acc1;
        float e2 = __ldg(&c2[j2]) - 2.f * acc2;
        int bi = dless(e2, j2, e1, j1) ? j2 : j1;
        chosen[tid] = bi;
        out[(size_t)(tok0 + tid) * QSTAGES + stage] = (float)bi;
    }
    __syncthreads();

    // residual update + commit partial + optional quantized output (fp32 exact)
    float4*       res4 = (float4*)g_res + (size_t)tok0 * 32;
    const float4* s4   = (const float4*)src + (size_t)tok0 * 32;
    const float4* x4   = (const float4*)x + (size_t)tok0 * 32;
    float4*       q4   = (float4*)(out + (size_t)TOKENS * QSTAGES) + (size_t)tok0 * 32;

    float psum = 0.f;
    #pragma unroll
    for (int k = 0; k < 16; k++) {
        int f = tid + k * NTHREADS;
        int tk = f >> 5, d4 = f & 31;
        float4 rv = s4[f];
        float4 cv = cb4[(size_t)chosen[tk] * 32 + d4];
        float4 nv = make_float4(rv.x - cv.x, rv.y - cv.y, rv.z - cv.z, rv.w - cv.w);
        res4[tk * 32 + d4] = nv;
        psum += nv.x * nv.x + nv.y * nv.y + nv.z * nv.z + nv.w * nv.w;
        if (is_last) {
            float4 xv = x4[f];
            q4[tk * 32 + d4] = make_float4(xv.x - nv.x, xv.y - nv.y,
                                           xv.z - nv.z, xv.w - nv.w);
        }
    }
    #pragma unroll
    for (int o = 16; o > 0; o >>= 1) psum += __shfl_down_sync(0xffffffffu, psum, o);
    __syncthreads();
    if (lid == 0) redv[wid] = psum;
    __syncthreads();
    if (tid == 0) {
        float s = 0.f;
        #pragma unroll
        for (int w2 = 0; w2 < 8; w2++) s += redv[w2];
        g_partial[stage * NBLOCKS + blockIdx.x] = s;
    }
}

// ---------------------------------------------------------------------------
__global__ void finish_kernel(float* __restrict__ out) {
    int q = threadIdx.x;
    if (q < QSTAGES) {
        float s = 0.f;
        for (int b = 0; b < NBLOCKS; b++) s += g_partial[q * NBLOCKS + b];
        out[(size_t)TOKENS * QSTAGES + (size_t)TOKENS * DDIM + q] =
            s / (float)(TOKENS * DDIM);
    }
}

extern "C" void kernel_launch(void* const* d_in, const int* in_sizes, int n_in,
                              void* d_out, int out_size) {
    const float* x  = (const float*)d_in[0];
    const float* cb = (const float*)d_in[1];
    float* out = (float*)d_out;

    cudaFuncSetAttribute(stage_kernel,
                         cudaFuncAttributeMaxDynamicSharedMemorySize, SMEM_TOTAL);

    prep_kernel<<<64, 128>>>(cb);
    c2_kernel<<<1024, 256>>>(cb);
    for (int s = 0; s < QSTAGES; s++) {
        stage_kernel<<<NBLOCKS, NTHREADS, SMEM_TOTAL>>>(x, cb, out, s,
                                                        (s == QSTAGES - 1) ? 1 : 0);
    }
    finish_kernel<<<1, 32>>>(out);
}